// round 12
// baseline (speedup 1.0000x reference)
#include <cuda_runtime.h>
#include <cstdint>

#define B_  16
#define N_  4096
#define S_  1024
#define C_  256
#define M_  (B_ * N_)   // 65536

// ---------------- scratch (no allocations allowed) ----------------
__device__ float g_interp[(size_t)M_ * C_];   // (B*N, 256) interpolated feats (tf32-rounded)
__device__ float g_y[(size_t)M_ * C_];        // GEMM1 output (pre-BN hidden)
__device__ float g_w1t[256 * 512];            // w1 pre-rounded to tf32
__device__ float g_w2t[256 * 256];            // w2 pre-rounded to tf32
__device__ int   g_idx[M_ * 3];
__device__ float g_w[M_ * 3];
__device__ float g_psum[512 * 256];
__device__ float g_psq [512 * 256];
__device__ float g_scale[256];
__device__ float g_shift[256];

// ---------------- PTX helpers (family-portable, sm_80+) ----------------
__device__ __forceinline__ uint32_t smem_u32(const void* p) {
    uint32_t a;
    asm("{ .reg .u64 t; cvta.to.shared.u64 t, %1; cvt.u32.u64 %0, t; }" : "=r"(a) : "l"(p));
    return a;
}
__device__ __forceinline__ uint32_t f2tf(float x) {
    uint32_t r; asm("cvt.rna.tf32.f32 %0, %1;" : "=r"(r) : "f"(x)); return r;
}
#define CP16(dst, src) \
    asm volatile("cp.async.cg.shared.global [%0], [%1], 16;" :: "r"(dst), "l"(src) : "memory")
#define CP_COMMIT() asm volatile("cp.async.commit_group;" ::: "memory")
#define CP_WAIT(N)  asm volatile("cp.async.wait_group %0;" :: "n"(N) : "memory")

#define MMA_TF32(c, a, b) \
    asm volatile("mma.sync.aligned.m16n8k8.row.col.f32.tf32.tf32.f32 " \
        "{%0,%1,%2,%3}, {%4,%5,%6,%7}, {%8,%9}, {%0,%1,%2,%3};" \
        : "+f"((c)[0]), "+f"((c)[1]), "+f"((c)[2]), "+f"((c)[3]) \
        : "r"((a)[0]), "r"((a)[1]), "r"((a)[2]), "r"((a)[3]), \
          "r"((b)[0]), "r"((b)[1]))

// ldmatrix x4 on b16 tiles == four 8x4 tf32 tiles; thread t gets tf32 (row t/4, col t%4)
#define LDSM4(r0, r1, r2, r3, addr) \
    asm volatile("ldmatrix.sync.aligned.m8n8.x4.shared.b16 {%0,%1,%2,%3}, [%4];" \
        : "=r"(r0), "=r"(r1), "=r"(r2), "=r"(r3) : "r"(addr))

// ---------------- prep: round weights to tf32 once ----------------
__global__ void prep_w_kernel(const float* __restrict__ w1,
                              const float* __restrict__ w2)
{
    int i = blockIdx.x * blockDim.x + threadIdx.x;
    if (i < 256 * 512) g_w1t[i] = __uint_as_float(f2tf(w1[i]));
    int j = i - 256 * 512;
    if (j >= 0 && j < 256 * 256) g_w2t[j] = __uint_as_float(f2tf(w2[j]));
}

// ---------------- 3-NN (idx + weights) ----------------
__global__ void knn_kernel(const float* __restrict__ xyz1,
                           const float* __restrict__ xyz2)
{
    __shared__ __align__(16) float4 sp[S_];
    int b = blockIdx.y;
    const float* X2 = xyz2 + (size_t)b * S_ * 3;
    for (int i = threadIdx.x; i < S_; i += blockDim.x) {
        float x = X2[i*3+0], y = X2[i*3+1], z = X2[i*3+2];
        sp[i] = make_float4(x, y, z, x*x + y*y + z*z);
    }
    __syncthreads();

    int n = blockIdx.x * blockDim.x + threadIdx.x;
    const float* p = xyz1 + ((size_t)b * N_ + n) * 3;
    float x1 = p[0], y1 = p[1], z1 = p[2];
    float s1 = x1*x1 + y1*y1 + z1*z1;

    float d0 = 3.4e38f, d1 = 3.4e38f, d2 = 3.4e38f;
    int   i0 = 0, i1 = 0, i2 = 0;
    #pragma unroll 4
    for (int s = 0; s < S_; s++) {
        float4 q = sp[s];
        float dot = fmaf(x1, q.x, fmaf(y1, q.y, z1 * q.z));
        float d   = fmaf(-2.0f, dot, s1 + q.w);
        if (d < d2) {
            if (d < d1) {
                d2 = d1; i2 = i1;
                if (d < d0) { d1 = d0; i1 = i0; d0 = d; i0 = s; }
                else        { d1 = d;  i1 = s; }
            } else { d2 = d; i2 = s; }
        }
    }
    float r0 = 1.0f / (d0 + 1e-8f);
    float r1 = 1.0f / (d1 + 1e-8f);
    float r2 = 1.0f / (d2 + 1e-8f);
    float inv = 1.0f / (r0 + r1 + r2);
    size_t o = ((size_t)b * N_ + n) * 3;
    g_idx[o+0] = i0; g_idx[o+1] = i1; g_idx[o+2] = i2;
    g_w[o+0] = r0 * inv; g_w[o+1] = r1 * inv; g_w[o+2] = r2 * inv;
}

// ---------------- gather + weighted interpolation (tf32-rounded out) ----------------
__global__ void interp_kernel(const float* __restrict__ points2)
{
    int lane = threadIdx.x & 31;
    int warp = threadIdx.x >> 5;
    size_t ng = (size_t)blockIdx.x * 8 + warp;
    int b = (int)(ng >> 12);

    const int*   id = g_idx + ng * 3;
    const float* wt = g_w   + ng * 3;
    int a0 = id[0], a1 = id[1], a2 = id[2];
    float w0 = wt[0], w1 = wt[1], w2 = wt[2];

    const float* P  = points2 + (size_t)b * S_ * C_;
    const float* p0 = P + (size_t)a0 * C_;
    const float* p1 = P + (size_t)a1 * C_;
    const float* p2 = P + (size_t)a2 * C_;
    float* out = g_interp + ng * C_;

    #pragma unroll
    for (int c = lane * 4; c < C_; c += 128) {
        float4 v0 = *(const float4*)(p0 + c);
        float4 v1 = *(const float4*)(p1 + c);
        float4 v2 = *(const float4*)(p2 + c);
        float4 o;
        o.x = __uint_as_float(f2tf(w0*v0.x + w1*v1.x + w2*v2.x));
        o.y = __uint_as_float(f2tf(w0*v0.y + w1*v1.y + w2*v2.y));
        o.z = __uint_as_float(f2tf(w0*v0.z + w1*v1.z + w2*v2.z));
        o.w = __uint_as_float(f2tf(w0*v0.w + w1*v1.w + w2*v2.w));
        *(float4*)(out + c) = o;
    }
}

// ---------------- tf32 mma.sync GEMM, 3-stage cp.async, 1 bar/chunk ----------------
// Y[m, n] = sum_k A[m, k] * W[n, k].  CTA tile 128x128, K chunks of 32, 3 smem stages.
// MODE 1: A = [points1 | g_interp] (K=512), W = g_w1t, Y = g_y
// MODE 2: A = relu(bn1(g_y)) fused at fragment load (K=256), W = g_w2t, Y = d_out
#define STG_FLOATS 4608                       // 128 rows * 36 (padded) per tile
#define GSM_FLOATS (6 * STG_FLOATS + 512)     // 3 stages x (A + B) + scale/shift
#define GSM_BYTES  (GSM_FLOATS * 4)           // 112640 B = 110 KB -> 2 CTAs/SM fits 228 KB

template<int MODE>
__global__ __launch_bounds__(256, 2)
void gemm_mma_kernel(const float* __restrict__ Aext,
                     float* __restrict__ Yext)
{
    extern __shared__ __align__(16) float smem[];
    float* s_scale = smem + 6 * STG_FLOATS;
    float* s_shift = s_scale + 256;

    const int NCH = (MODE == 1) ? 16 : 8;
    const int KW  = (MODE == 1) ? 512 : 256;
    const float* W = (MODE == 1) ? (const float*)g_w1t : (const float*)g_w2t;
    float* Y = (MODE == 1) ? (float*)g_y : Yext;

    const int tid  = threadIdx.x;
    const int lane = tid & 31;
    const int wid  = tid >> 5;
    const int wm   = wid & 3;          // 4 warps along m (32 rows each)
    const int wn   = wid >> 2;         // 2 warps along n (64 cols each)
    const int m0   = blockIdx.y * 128;
    const int n0   = blockIdx.x * 128;

    if (MODE == 2 && tid < 256) {
        s_scale[tid] = g_scale[tid];
        s_shift[tid] = g_shift[tid];
    }

    const uint32_t smem_b = smem_u32(smem);
    uint32_t sA[3], sB[3];
    #pragma unroll
    for (int s = 0; s < 3; s++) {
        sA[s] = smem_b + s * (STG_FLOATS * 4);
        sB[s] = smem_b + (3 + s) * (STG_FLOATS * 4);
    }
    const int lrow = tid >> 3;
    const int lc4  = tid & 7;

    auto cp_chunk = [&](int kt, int stg) {
        const float* Asrc; int acol;
        if (MODE == 1) {
            if (kt < 8) { Asrc = Aext;                    acol = kt * 32; }
            else        { Asrc = (const float*)g_interp;  acol = (kt - 8) * 32; }
        } else          { Asrc = (const float*)g_y;       acol = kt * 32; }
        const int kcol = kt * 32;
        #pragma unroll
        for (int i = 0; i < 4; i++) {
            int row = lrow + i * 32;
            uint32_t soff = (uint32_t)(row * 144 + lc4 * 16);
            CP16(sA[stg] + soff, Asrc + (size_t)(m0 + row) * C_ + acol + lc4 * 4);
            CP16(sB[stg] + soff, W    + (size_t)(n0 + row) * KW + kcol + lc4 * 4);
        }
        CP_COMMIT();
    };

    float c[2][8][4];
    #pragma unroll
    for (int mt = 0; mt < 2; mt++)
        #pragma unroll
        for (int nt = 0; nt < 8; nt++)
            #pragma unroll
            for (int j = 0; j < 4; j++) c[mt][nt][j] = 0.f;

    // prologue: stages 0, 1 in flight
    cp_chunk(0, 0);
    cp_chunk(1, 1);

    const int qk = lane & 3;     // k offset within frag
    const int qr = lane >> 2;    // row offset within frag

    const int lg  = lane >> 3;   // ldmatrix tile index 0..3
    const int lr8 = lane & 7;    // row within tile
    const uint32_t aoff = (uint32_t)(((wm * 32 + (lg & 1) * 8 + lr8) * 36 + (lg >> 1) * 4) * 4);
    const uint32_t boff = (uint32_t)(((wn * 64 + (lg >> 1) * 8 + lr8) * 36 + (lg & 1) * 4) * 4);

    int stg = 0;
    for (int kt = 0; kt < NCH; kt++) {
        CP_WAIT(1);              // retires group kt (one group committed per iter below)
        __syncthreads();         // chunk kt resident; all warps done with stage (kt-1)%3

        // issue next fill immediately (targets stage (kt-1)%3, safe after the bar);
        // empty commit keeps the group count aligned so CP_WAIT(1) stays correct
        if (kt + 2 < NCH) { int ns = stg + 2; if (ns >= 3) ns -= 3; cp_chunk(kt + 2, ns); }
        else              { CP_COMMIT(); }

        const uint32_t aBase = sA[stg] + aoff;
        const uint32_t bBase = sB[stg] + boff;

        #pragma unroll
        for (int ks = 0; ks < 4; ks++) {
            uint32_t a[2][4];
            #pragma unroll
            for (int mt = 0; mt < 2; mt++) {
                uint32_t r0, r1, r2, r3;
                LDSM4(r0, r1, r2, r3, aBase + mt * (16 * 144) + ks * 32);
                float v0 = __uint_as_float(r0), v1 = __uint_as_float(r1);
                float v2 = __uint_as_float(r2), v3 = __uint_as_float(r3);
                if (MODE == 2) {
                    int ch0 = kt * 32 + ks * 8 + qk;
                    int ch1 = ch0 + 4;
                    float sc0 = s_scale[ch0], sh0 = s_shift[ch0];
                    float sc1 = s_scale[ch1], sh1 = s_shift[ch1];
                    v0 = fmaxf(fmaf(v0, sc0, sh0), 0.f);
                    v1 = fmaxf(fmaf(v1, sc0, sh0), 0.f);
                    v2 = fmaxf(fmaf(v2, sc1, sh1), 0.f);
                    v3 = fmaxf(fmaf(v3, sc1, sh1), 0.f);
                }
                a[mt][0] = f2tf(v0); a[mt][1] = f2tf(v1);
                a[mt][2] = f2tf(v2); a[mt][3] = f2tf(v3);
            }
            uint32_t b[8][2];
            #pragma unroll
            for (int nt2 = 0; nt2 < 4; nt2++) {
                LDSM4(b[2*nt2][0], b[2*nt2][1], b[2*nt2+1][0], b[2*nt2+1][1],
                      bBase + nt2 * (16 * 144) + ks * 32);   // B pre-rounded tf32
            }
            #pragma unroll
            for (int mt = 0; mt < 2; mt++)
                #pragma unroll
                for (int nt = 0; nt < 8; nt++)
                    MMA_TF32(c[mt][nt], a[mt], b[nt]);
        }

        if (++stg == 3) stg = 0;
    }

    // ---- epilogue: write Y ----
    #pragma unroll
    for (int mt = 0; mt < 2; mt++) {
        int row = m0 + wm * 32 + mt * 16 + qr;
        #pragma unroll
        for (int nt = 0; nt < 8; nt++) {
            int col = n0 + wn * 64 + nt * 8 + 2 * qk;
            *(float2*)&Y[(size_t)row * 256 + col] =
                make_float2(c[mt][nt][0], c[mt][nt][1]);
            *(float2*)&Y[(size_t)(row + 8) * 256 + col] =
                make_float2(c[mt][nt][2], c[mt][nt][3]);
        }
    }

    __syncthreads();   // all warps done with LDSM before smem is reused for stats

    // ---- fused BN stats: per-column partial sum / sumsq over this CTA's 128 rows ----
    float* s_sum = smem;         // [4][128]
    float* s_sq  = smem + 512;   // [4][128]
    #pragma unroll
    for (int nt = 0; nt < 8; nt++) {
        #pragma unroll
        for (int p = 0; p < 2; p++) {
            float v0 = c[0][nt][p],     v1 = c[0][nt][p + 2];
            float v2 = c[1][nt][p],     v3 = c[1][nt][p + 2];
            float s  = (v0 + v1) + (v2 + v3);
            float s2 = fmaf(v0, v0, fmaf(v1, v1, fmaf(v2, v2, v3 * v3)));
            #pragma unroll
            for (int off = 4; off <= 16; off <<= 1) {
                s  += __shfl_xor_sync(0xFFFFFFFFu, s,  off);
                s2 += __shfl_xor_sync(0xFFFFFFFFu, s2, off);
            }
            if (qr == 0) {
                int col = wn * 64 + nt * 8 + 2 * qk + p;   // 0..127
                s_sum[wm * 128 + col] = s;
                s_sq [wm * 128 + col] = s2;
            }
        }
    }
    __syncthreads();
    if (tid < 128) {
        int col = tid;
        float s  = (s_sum[col] + s_sum[128 + col]) + (s_sum[256 + col] + s_sum[384 + col]);
        float s2 = (s_sq [col] + s_sq [128 + col]) + (s_sq [256 + col] + s_sq [384 + col]);
        size_t slot = (size_t)blockIdx.y * 256 + blockIdx.x * 128 + col;
        g_psum[slot] = s;
        g_psq [slot] = s2;
    }
}

// ---------------- BN finalize ----------------
__global__ void stats_finalize_kernel(const float* __restrict__ gamma,
                                      const float* __restrict__ beta)
{
    int c = threadIdx.x;
    float s = 0.f, s2 = 0.f;
    for (int i = 0; i < 512; i++) {
        s  += g_psum[i * 256 + c];
        s2 += g_psq [i * 256 + c];
    }
    const float invM = 1.0f / 65536.0f;
    float mu   = s * invM;
    float var  = fmaf(-mu, mu, s2 * invM);
    float rstd = rsqrtf(var + 1e-5f);
    float sc   = rstd * gamma[c];
    g_scale[c] = sc;
    g_shift[c] = fmaf(-mu, sc, beta[c]);
}

__global__ void norm_relu_kernel(float* Y)
{
    size_t i = (size_t)blockIdx.x * blockDim.x + threadIdx.x;  // float4 index
    int cg = (int)(i & 63) * 4;
    float4 v = *((float4*)Y + i);
    v.x = fmaxf(fmaf(v.x, __ldg(&g_scale[cg+0]), __ldg(&g_shift[cg+0])), 0.f);
    v.y = fmaxf(fmaf(v.y, __ldg(&g_scale[cg+1]), __ldg(&g_shift[cg+1])), 0.f);
    v.z = fmaxf(fmaf(v.z, __ldg(&g_scale[cg+2]), __ldg(&g_shift[cg+2])), 0.f);
    v.w = fmaxf(fmaf(v.w, __ldg(&g_scale[cg+3]), __ldg(&g_shift[cg+3])), 0.f);
    *((float4*)Y + i) = v;
}

// ---------------- launch ----------------
extern "C" void kernel_launch(void* const* d_in, const int* in_sizes, int n_in,
                              void* d_out, int out_size)
{
    const float* xyz1    = (const float*)d_in[0];
    const float* xyz2    = (const float*)d_in[1];
    const float* points1 = (const float*)d_in[2];
    const float* points2 = (const float*)d_in[3];
    const float* w1      = (const float*)d_in[4];
    const float* g1      = (const float*)d_in[5];
    const float* b1      = (const float*)d_in[6];
    const float* w2      = (const float*)d_in[7];
    const float* g2      = (const float*)d_in[8];
    const float* b2      = (const float*)d_in[9];
    float* out = (float*)d_out;

    cudaFuncSetAttribute(gemm_mma_kernel<1>, cudaFuncAttributeMaxDynamicSharedMemorySize, GSM_BYTES);
    cudaFuncSetAttribute(gemm_mma_kernel<2>, cudaFuncAttributeMaxDynamicSharedMemorySize, GSM_BYTES);

    prep_w_kernel<<<768, 256>>>(w1, w2);
    knn_kernel<<<dim3(N_ / 256, B_), 256>>>(xyz1, xyz2);
    interp_kernel<<<M_ / 8, 256>>>(points2);

    gemm_mma_kernel<1><<<dim3(2, 512), 256, GSM_BYTES>>>(points1, nullptr);   // + stats
    stats_finalize_kernel<<<1, 256>>>(g1, b1);

    gemm_mma_kernel<2><<<dim3(2, 512), 256, GSM_BYTES>>>(nullptr, out);       // + stats
    stats_finalize_kernel<<<1, 256>>>(g2, b2);
    norm_relu_kernel<<<16384, 256>>>(out);
}

// round 13
// speedup vs baseline: 1.1259x; 1.1259x over previous
#include <cuda_runtime.h>
#include <cstdint>

#define B_  16
#define N_  4096
#define S_  1024
#define C_  256
#define M_  (B_ * N_)   // 65536

// ---------------- scratch (no allocations allowed) ----------------
__device__ float g_z[(size_t)B_ * S_ * C_];   // Z = points2 @ w1[:,256:512]^T  (16384 x 256)
__device__ float g_y[(size_t)M_ * C_];        // GEMM1 output (pre-BN hidden)
__device__ float g_w1t[256 * 512];            // w1 pre-rounded to tf32
__device__ float g_w2t[256 * 256];            // w2 pre-rounded to tf32
__device__ int   g_idx[M_ * 3];
__device__ float g_w[M_ * 3];
__device__ float g_psum[512 * 256];
__device__ float g_psq [512 * 256];
__device__ float g_scale[256];
__device__ float g_shift[256];

// ---------------- PTX helpers (family-portable, sm_80+) ----------------
__device__ __forceinline__ uint32_t smem_u32(const void* p) {
    uint32_t a;
    asm("{ .reg .u64 t; cvta.to.shared.u64 t, %1; cvt.u32.u64 %0, t; }" : "=r"(a) : "l"(p));
    return a;
}
__device__ __forceinline__ uint32_t f2tf(float x) {
    uint32_t r; asm("cvt.rna.tf32.f32 %0, %1;" : "=r"(r) : "f"(x)); return r;
}
#define CP16(dst, src) \
    asm volatile("cp.async.cg.shared.global [%0], [%1], 16;" :: "r"(dst), "l"(src) : "memory")
#define CP_COMMIT() asm volatile("cp.async.commit_group;" ::: "memory")
#define CP_WAIT(N)  asm volatile("cp.async.wait_group %0;" :: "n"(N) : "memory")

#define MMA_TF32(c, a, b) \
    asm volatile("mma.sync.aligned.m16n8k8.row.col.f32.tf32.tf32.f32 " \
        "{%0,%1,%2,%3}, {%4,%5,%6,%7}, {%8,%9}, {%0,%1,%2,%3};" \
        : "+f"((c)[0]), "+f"((c)[1]), "+f"((c)[2]), "+f"((c)[3]) \
        : "r"((a)[0]), "r"((a)[1]), "r"((a)[2]), "r"((a)[3]), \
          "r"((b)[0]), "r"((b)[1]))

// ldmatrix x4 on b16 tiles == four 8x4 tf32 tiles; thread t gets tf32 (row t/4, col t%4)
#define LDSM4(r0, r1, r2, r3, addr) \
    asm volatile("ldmatrix.sync.aligned.m8n8.x4.shared.b16 {%0,%1,%2,%3}, [%4];" \
        : "=r"(r0), "=r"(r1), "=r"(r2), "=r"(r3) : "r"(addr))

// ---------------- prep: round weights to tf32 once ----------------
__global__ void prep_w_kernel(const float* __restrict__ w1,
                              const float* __restrict__ w2)
{
    int i = blockIdx.x * blockDim.x + threadIdx.x;
    if (i < 256 * 512) g_w1t[i] = __uint_as_float(f2tf(w1[i]));
    int j = i - 256 * 512;
    if (j >= 0 && j < 256 * 256) g_w2t[j] = __uint_as_float(f2tf(w2[j]));
}

// ---------------- 3-NN (idx + weights) ----------------
__global__ void knn_kernel(const float* __restrict__ xyz1,
                           const float* __restrict__ xyz2)
{
    __shared__ __align__(16) float4 sp[S_];
    int b = blockIdx.y;
    const float* X2 = xyz2 + (size_t)b * S_ * 3;
    for (int i = threadIdx.x; i < S_; i += blockDim.x) {
        float x = X2[i*3+0], y = X2[i*3+1], z = X2[i*3+2];
        sp[i] = make_float4(x, y, z, x*x + y*y + z*z);
    }
    __syncthreads();

    int n = blockIdx.x * blockDim.x + threadIdx.x;
    const float* p = xyz1 + ((size_t)b * N_ + n) * 3;
    float x1 = p[0], y1 = p[1], z1 = p[2];
    float s1 = x1*x1 + y1*y1 + z1*z1;

    float d0 = 3.4e38f, d1 = 3.4e38f, d2 = 3.4e38f;
    int   i0 = 0, i1 = 0, i2 = 0;
    #pragma unroll 4
    for (int s = 0; s < S_; s++) {
        float4 q = sp[s];
        float dot = fmaf(x1, q.x, fmaf(y1, q.y, z1 * q.z));
        float d   = fmaf(-2.0f, dot, s1 + q.w);
        if (d < d2) {
            if (d < d1) {
                d2 = d1; i2 = i1;
                if (d < d0) { d1 = d0; i1 = i0; d0 = d; i0 = s; }
                else        { d1 = d;  i1 = s; }
            } else { d2 = d; i2 = s; }
        }
    }
    float r0 = 1.0f / (d0 + 1e-8f);
    float r1 = 1.0f / (d1 + 1e-8f);
    float r2 = 1.0f / (d2 + 1e-8f);
    float inv = 1.0f / (r0 + r1 + r2);
    size_t o = ((size_t)b * N_ + n) * 3;
    g_idx[o+0] = i0; g_idx[o+1] = i1; g_idx[o+2] = i2;
    g_w[o+0] = r0 * inv; g_w[o+1] = r1 * inv; g_w[o+2] = r2 * inv;
}

// ---------------- tf32 mma.sync GEMM (2-stage cp.async, ldmatrix) ----------------
// All modes: K = 256, CTA tile 128x128.
// MODE 3: Z = points2 @ w1[:,256:]^T          (grid 2 x 128, Y = g_z)
// MODE 1: Y = points1 @ w1[:,:256]^T, then epilogue += sum_j w_j * Z[idx_j],
//         fused BN stats                       (grid 2 x 512, Y = g_y)
// MODE 2: A = relu(bn1(g_y)) fused at fragment load, Y = d_out, fused BN stats
#define GSM_FLOATS (4 * 128 * 36 + 512)
#define GSM_BYTES  (GSM_FLOATS * 4)

template<int MODE>
__global__ __launch_bounds__(256, 2)
void gemm_mma_kernel(const float* __restrict__ Aext,
                     float* __restrict__ Yext)
{
    extern __shared__ __align__(16) float smem[];
    float* Abuf[2] = { smem,        smem + 4608 };
    float* Bbuf[2] = { smem + 9216, smem + 13824 };
    float* s_scale = smem + 18432;
    float* s_shift = s_scale + 256;

    const int NCH = 8;                                   // K = 256 everywhere
    const int KW  = (MODE == 2) ? 256 : 512;             // w1 rows have length 512
    const float* W = (MODE == 1) ? (const float*)g_w1t
                   : (MODE == 2) ? (const float*)g_w2t
                                 : (const float*)g_w1t + 256;   // cols 256:512
    float* Y = (MODE == 1) ? (float*)g_y
             : (MODE == 3) ? (float*)g_z
                           : Yext;

    const int tid  = threadIdx.x;
    const int lane = tid & 31;
    const int wid  = tid >> 5;
    const int wm   = wid & 3;          // 4 warps along m (32 rows each)
    const int wn   = wid >> 2;         // 2 warps along n (64 cols each)
    const int m0   = blockIdx.y * 128;
    const int n0   = blockIdx.x * 128;

    if (MODE == 2 && tid < 256) {
        s_scale[tid] = g_scale[tid];
        s_shift[tid] = g_shift[tid];
    }

    const uint32_t sA[2] = { smem_u32(Abuf[0]), smem_u32(Abuf[1]) };
    const uint32_t sB[2] = { smem_u32(Bbuf[0]), smem_u32(Bbuf[1]) };
    const int lrow = tid >> 3;
    const int lc4  = tid & 7;

    auto cp_chunk = [&](int kt, int buf) {
        const float* Asrc = (MODE == 2) ? (const float*)g_y : Aext;
        const int kcol = kt * 32;
        #pragma unroll
        for (int i = 0; i < 4; i++) {
            int row = lrow + i * 32;
            uint32_t soff = (uint32_t)(row * 144 + lc4 * 16);
            CP16(sA[buf] + soff, Asrc + (size_t)(m0 + row) * C_ + kcol + lc4 * 4);
            CP16(sB[buf] + soff, W    + (size_t)(n0 + row) * KW + kcol + lc4 * 4);
        }
        CP_COMMIT();
    };

    float c[2][8][4];
    #pragma unroll
    for (int mt = 0; mt < 2; mt++)
        #pragma unroll
        for (int nt = 0; nt < 8; nt++)
            #pragma unroll
            for (int j = 0; j < 4; j++) c[mt][nt][j] = 0.f;

    cp_chunk(0, 0);

    const int qk = lane & 3;     // k offset within frag
    const int qr = lane >> 2;    // row offset within frag

    const int lg  = lane >> 3;   // ldmatrix tile index 0..3
    const int lr8 = lane & 7;    // row within tile
    const uint32_t aoff = (uint32_t)(((wm * 32 + (lg & 1) * 8 + lr8) * 36 + (lg >> 1) * 4) * 4);
    const uint32_t boff = (uint32_t)(((wn * 64 + (lg >> 1) * 8 + lr8) * 36 + (lg & 1) * 4) * 4);

    for (int kt = 0; kt < NCH; kt++) {
        int buf = kt & 1;
        if (kt + 1 < NCH) { cp_chunk(kt + 1, buf ^ 1); CP_WAIT(1); }
        else              { CP_WAIT(0); }
        __syncthreads();

        const uint32_t aBase = sA[buf] + aoff;
        const uint32_t bBase = sB[buf] + boff;

        #pragma unroll
        for (int ks = 0; ks < 4; ks++) {
            uint32_t a[2][4];
            #pragma unroll
            for (int mt = 0; mt < 2; mt++) {
                uint32_t r0, r1, r2, r3;
                LDSM4(r0, r1, r2, r3, aBase + mt * (16 * 144) + ks * 32);
                float v0 = __uint_as_float(r0), v1 = __uint_as_float(r1);
                float v2 = __uint_as_float(r2), v3 = __uint_as_float(r3);
                if (MODE == 2) {
                    int ch0 = kt * 32 + ks * 8 + qk;
                    int ch1 = ch0 + 4;
                    float sc0 = s_scale[ch0], sh0 = s_shift[ch0];
                    float sc1 = s_scale[ch1], sh1 = s_shift[ch1];
                    v0 = fmaxf(fmaf(v0, sc0, sh0), 0.f);
                    v1 = fmaxf(fmaf(v1, sc0, sh0), 0.f);
                    v2 = fmaxf(fmaf(v2, sc1, sh1), 0.f);
                    v3 = fmaxf(fmaf(v3, sc1, sh1), 0.f);
                }
                a[mt][0] = f2tf(v0); a[mt][1] = f2tf(v1);
                a[mt][2] = f2tf(v2); a[mt][3] = f2tf(v3);
            }
            uint32_t b[8][2];
            #pragma unroll
            for (int nt2 = 0; nt2 < 4; nt2++) {
                LDSM4(b[2*nt2][0], b[2*nt2][1], b[2*nt2+1][0], b[2*nt2+1][1],
                      bBase + nt2 * (16 * 144) + ks * 32);   // B pre-rounded tf32
            }
            #pragma unroll
            for (int mt = 0; mt < 2; mt++)
                #pragma unroll
                for (int nt = 0; nt < 8; nt++)
                    MMA_TF32(c[mt][nt], a[mt], b[nt]);
        }
        __syncthreads();
    }

    // ---- MODE 1: add interpolated contribution  sum_j w_j * Z[idx_j]  (fp32) ----
    if (MODE == 1) {
        #pragma unroll
        for (int mt = 0; mt < 2; mt++) {
            #pragma unroll
            for (int h = 0; h < 2; h++) {
                int gr = m0 + wm * 32 + mt * 16 + qr + h * 8;    // global point id
                const int*   id = g_idx + (size_t)gr * 3;
                const float* wt = g_w   + (size_t)gr * 3;
                int bb = (gr >> 12) << 10;                       // batch * S_
                const float* Z0 = g_z + (size_t)(bb + id[0]) * 256;
                const float* Z1 = g_z + (size_t)(bb + id[1]) * 256;
                const float* Z2 = g_z + (size_t)(bb + id[2]) * 256;
                float w0 = wt[0], w1 = wt[1], w2 = wt[2];
                #pragma unroll
                for (int nt = 0; nt < 8; nt++) {
                    int col = n0 + wn * 64 + nt * 8 + 2 * qk;
                    float2 z0 = *(const float2*)(Z0 + col);
                    float2 z1 = *(const float2*)(Z1 + col);
                    float2 z2 = *(const float2*)(Z2 + col);
                    c[mt][nt][2*h+0] += w0*z0.x + w1*z1.x + w2*z2.x;
                    c[mt][nt][2*h+1] += w0*z0.y + w1*z1.y + w2*z2.y;
                }
            }
        }
    }

    // ---- epilogue: write Y ----
    #pragma unroll
    for (int mt = 0; mt < 2; mt++) {
        int row = m0 + wm * 32 + mt * 16 + qr;
        #pragma unroll
        for (int nt = 0; nt < 8; nt++) {
            int col = n0 + wn * 64 + nt * 8 + 2 * qk;
            *(float2*)&Y[(size_t)row * 256 + col] =
                make_float2(c[mt][nt][0], c[mt][nt][1]);
            *(float2*)&Y[(size_t)(row + 8) * 256 + col] =
                make_float2(c[mt][nt][2], c[mt][nt][3]);
        }
    }

    // ---- fused BN stats (MODE 1 and 2 only) ----
    if (MODE != 3) {
        float* s_sum = smem;         // [4][128]
        float* s_sq  = smem + 512;   // [4][128]
        #pragma unroll
        for (int nt = 0; nt < 8; nt++) {
            #pragma unroll
            for (int p = 0; p < 2; p++) {
                float v0 = c[0][nt][p],     v1 = c[0][nt][p + 2];
                float v2 = c[1][nt][p],     v3 = c[1][nt][p + 2];
                float s  = (v0 + v1) + (v2 + v3);
                float s2 = fmaf(v0, v0, fmaf(v1, v1, fmaf(v2, v2, v3 * v3)));
                #pragma unroll
                for (int off = 4; off <= 16; off <<= 1) {
                    s  += __shfl_xor_sync(0xFFFFFFFFu, s,  off);
                    s2 += __shfl_xor_sync(0xFFFFFFFFu, s2, off);
                }
                if (qr == 0) {
                    int col = wn * 64 + nt * 8 + 2 * qk + p;   // 0..127
                    s_sum[wm * 128 + col] = s;
                    s_sq [wm * 128 + col] = s2;
                }
            }
        }
        __syncthreads();
        if (tid < 128) {
            int col = tid;
            float s  = (s_sum[col] + s_sum[128 + col]) + (s_sum[256 + col] + s_sum[384 + col]);
            float s2 = (s_sq [col] + s_sq [128 + col]) + (s_sq [256 + col] + s_sq [384 + col]);
            size_t slot = (size_t)blockIdx.y * 256 + blockIdx.x * 128 + col;
            g_psum[slot] = s;
            g_psq [slot] = s2;
        }
    }
}

// ---------------- BN finalize ----------------
__global__ void stats_finalize_kernel(const float* __restrict__ gamma,
                                      const float* __restrict__ beta)
{
    int c = threadIdx.x;
    float s = 0.f, s2 = 0.f;
    for (int i = 0; i < 512; i++) {
        s  += g_psum[i * 256 + c];
        s2 += g_psq [i * 256 + c];
    }
    const float invM = 1.0f / 65536.0f;
    float mu   = s * invM;
    float var  = fmaf(-mu, mu, s2 * invM);
    float rstd = rsqrtf(var + 1e-5f);
    float sc   = rstd * gamma[c];
    g_scale[c] = sc;
    g_shift[c] = fmaf(-mu, sc, beta[c]);
}

__global__ void norm_relu_kernel(float* Y)
{
    size_t i = (size_t)blockIdx.x * blockDim.x + threadIdx.x;  // float4 index
    int cg = (int)(i & 63) * 4;
    float4 v = *((float4*)Y + i);
    v.x = fmaxf(fmaf(v.x, __ldg(&g_scale[cg+0]), __ldg(&g_shift[cg+0])), 0.f);
    v.y = fmaxf(fmaf(v.y, __ldg(&g_scale[cg+1]), __ldg(&g_shift[cg+1])), 0.f);
    v.z = fmaxf(fmaf(v.z, __ldg(&g_scale[cg+2]), __ldg(&g_shift[cg+2])), 0.f);
    v.w = fmaxf(fmaf(v.w, __ldg(&g_scale[cg+3]), __ldg(&g_shift[cg+3])), 0.f);
    *((float4*)Y + i) = v;
}

// ---------------- launch ----------------
extern "C" void kernel_launch(void* const* d_in, const int* in_sizes, int n_in,
                              void* d_out, int out_size)
{
    const float* xyz1    = (const float*)d_in[0];
    const float* xyz2    = (const float*)d_in[1];
    const float* points1 = (const float*)d_in[2];
    const float* points2 = (const float*)d_in[3];
    const float* w1      = (const float*)d_in[4];
    const float* g1      = (const float*)d_in[5];
    const float* b1      = (const float*)d_in[6];
    const float* w2      = (const float*)d_in[7];
    const float* g2      = (const float*)d_in[8];
    const float* b2      = (const float*)d_in[9];
    float* out = (float*)d_out;

    cudaFuncSetAttribute(gemm_mma_kernel<1>, cudaFuncAttributeMaxDynamicSharedMemorySize, GSM_BYTES);
    cudaFuncSetAttribute(gemm_mma_kernel<2>, cudaFuncAttributeMaxDynamicSharedMemorySize, GSM_BYTES);
    cudaFuncSetAttribute(gemm_mma_kernel<3>, cudaFuncAttributeMaxDynamicSharedMemorySize, GSM_BYTES);

    prep_w_kernel<<<768, 256>>>(w1, w2);
    knn_kernel<<<dim3(N_ / 256, B_), 256>>>(xyz1, xyz2);

    // Z = points2 @ w1[:,256:]^T   (16384 x 256)
    gemm_mma_kernel<3><<<dim3(2, 128), 256, GSM_BYTES>>>(points2, nullptr);

    // Y = points1 @ w1[:,:256]^T + gather(Z)  (+ fused stats)
    gemm_mma_kernel<1><<<dim3(2, 512), 256, GSM_BYTES>>>(points1, nullptr);
    stats_finalize_kernel<<<1, 256>>>(g1, b1);

    // out = relu(bn1(Y)) @ w2^T  (+ fused stats)
    gemm_mma_kernel<2><<<dim3(2, 512), 256, GSM_BYTES>>>(nullptr, out);
    stats_finalize_kernel<<<1, 256>>>(g2, b2);
    norm_relu_kernel<<<16384, 256>>>(out);
}

// round 16
// speedup vs baseline: 1.3557x; 1.2041x over previous
#include <cuda_runtime.h>
#include <cuda_fp16.h>
#include <cstdint>

#define B_  16
#define N_  4096
#define S_  1024
#define C_  256
#define M_  (B_ * N_)   // 65536

// ---------------- scratch (no allocations allowed) ----------------
__device__ __half g_p1h[(size_t)M_ * C_];        // points1 fp16
__device__ __half g_p2h[(size_t)B_ * S_ * C_];   // points2 fp16
__device__ __half g_w1h[256 * 512];              // w1 fp16
__device__ __half g_w2h[256 * 256];              // w2 fp16
__device__ __half g_yh[(size_t)M_ * C_];         // hidden y fp16 (pre-BN)
__device__ float  g_z[(size_t)B_ * S_ * C_];     // Z = points2 @ w1[:,256:]^T (fp32)
__device__ int    g_idx[M_ * 3];
__device__ float  g_w[M_ * 3];
__device__ float  g_psum[512 * 256];
__device__ float  g_psq [512 * 256];
__device__ float  g_scale[256];
__device__ float  g_shift[256];

// ---------------- PTX helpers (family-portable, sm_80+) ----------------
__device__ __forceinline__ uint32_t smem_u32(const void* p) {
    uint32_t a;
    asm("{ .reg .u64 t; cvta.to.shared.u64 t, %1; cvt.u32.u64 %0, t; }" : "=r"(a) : "l"(p));
    return a;
}
#define CP16(dst, src) \
    asm volatile("cp.async.cg.shared.global [%0], [%1], 16;" :: "r"(dst), "l"(src) : "memory")
#define CP_COMMIT() asm volatile("cp.async.commit_group;" ::: "memory")
#define CP_WAIT(N)  asm volatile("cp.async.wait_group %0;" :: "n"(N) : "memory")

#define MMA_F16(c, a, b) \
    asm volatile("mma.sync.aligned.m16n8k16.row.col.f32.f16.f16.f32 " \
        "{%0,%1,%2,%3}, {%4,%5,%6,%7}, {%8,%9}, {%0,%1,%2,%3};" \
        : "+f"((c)[0]), "+f"((c)[1]), "+f"((c)[2]), "+f"((c)[3]) \
        : "r"((a)[0]), "r"((a)[1]), "r"((a)[2]), "r"((a)[3]), \
          "r"((b)[0]), "r"((b)[1]))

#define LDSM4(r0, r1, r2, r3, addr) \
    asm volatile("ldmatrix.sync.aligned.m8n8.x4.shared.b16 {%0,%1,%2,%3}, [%4];" \
        : "=r"(r0), "=r"(r1), "=r"(r2), "=r"(r3) : "r"(addr))

// ---------------- prep: convert inputs to fp16 once ----------------
#define S1_ (M_ * C_ / 4)                 // points1 float4 count
#define S2_ (B_ * S_ * C_ / 4)
#define S3_ (256 * 512 / 4)
#define S4_ (256 * 256 / 4)
__global__ void prep_convert_kernel(const float* __restrict__ p1,
                                    const float* __restrict__ p2,
                                    const float* __restrict__ w1,
                                    const float* __restrict__ w2)
{
    size_t i = (size_t)blockIdx.x * blockDim.x + threadIdx.x;
    const float4* src; __half2* dst; size_t off;
    if      (i < S1_)                 { src = (const float4*)p1; dst = (__half2*)g_p1h; off = i; }
    else if (i < S1_ + S2_)           { src = (const float4*)p2; dst = (__half2*)g_p2h; off = i - S1_; }
    else if (i < S1_ + S2_ + S3_)     { src = (const float4*)w1; dst = (__half2*)g_w1h; off = i - S1_ - S2_; }
    else if (i < S1_ + S2_ + S3_ + S4_){ src = (const float4*)w2; dst = (__half2*)g_w2h; off = i - S1_ - S2_ - S3_; }
    else return;
    float4 v = src[off];
    dst[off * 2 + 0] = __floats2half2_rn(v.x, v.y);
    dst[off * 2 + 1] = __floats2half2_rn(v.z, v.w);
}

// ---------------- 3-NN (idx + weights) ----------------
__global__ void knn_kernel(const float* __restrict__ xyz1,
                           const float* __restrict__ xyz2)
{
    __shared__ __align__(16) float4 sp[S_];
    int b = blockIdx.y;
    const float* X2 = xyz2 + (size_t)b * S_ * 3;
    for (int i = threadIdx.x; i < S_; i += blockDim.x) {
        float x = X2[i*3+0], y = X2[i*3+1], z = X2[i*3+2];
        sp[i] = make_float4(x, y, z, x*x + y*y + z*z);
    }
    __syncthreads();

    int n = blockIdx.x * blockDim.x + threadIdx.x;
    const float* p = xyz1 + ((size_t)b * N_ + n) * 3;
    float x1 = p[0], y1 = p[1], z1 = p[2];
    float s1 = x1*x1 + y1*y1 + z1*z1;

    float d0 = 3.4e38f, d1 = 3.4e38f, d2 = 3.4e38f;
    int   i0 = 0, i1 = 0, i2 = 0;
    #pragma unroll 4
    for (int s = 0; s < S_; s++) {
        float4 q = sp[s];
        float dot = fmaf(x1, q.x, fmaf(y1, q.y, z1 * q.z));
        float d   = fmaf(-2.0f, dot, s1 + q.w);
        if (d < d2) {
            if (d < d1) {
                d2 = d1; i2 = i1;
                if (d < d0) { d1 = d0; i1 = i0; d0 = d; i0 = s; }
                else        { d1 = d;  i1 = s; }
            } else { d2 = d; i2 = s; }
        }
    }
    float r0 = 1.0f / (d0 + 1e-8f);
    float r1 = 1.0f / (d1 + 1e-8f);
    float r2 = 1.0f / (d2 + 1e-8f);
    float inv = 1.0f / (r0 + r1 + r2);
    size_t o = ((size_t)b * N_ + n) * 3;
    g_idx[o+0] = i0; g_idx[o+1] = i1; g_idx[o+2] = i2;
    g_w[o+0] = r0 * inv; g_w[o+1] = r1 * inv; g_w[o+2] = r2 * inv;
}

// ---------------- fp16 mma.sync GEMM (2-stage cp.async, ldmatrix) ----------------
// All modes: K = 256 (4 chunks of 64), CTA tile 128x128.
// A source resolved INSIDE device code (never pass __device__ symbols from host!):
// MODE 3: A = g_p2h, W = w1[:,256:] -> g_z fp32           (grid 2 x 128)
// MODE 1: A = g_p1h, W = w1[:,:256], + gather(Z) -> g_yh fp16, fused BN stats (grid 2 x 512)
// MODE 2: A = relu(bn1(g_yh)) half2-fused, W = w2 -> d_out fp32, fused BN stats
#define STG_B  18432                     // 128 rows * 144 bytes
#define GSM_BYTES (4 * STG_B + 1024)     // 74752 B

template<int MODE>
__global__ __launch_bounds__(256, 2)
void gemm_mma_kernel(float* __restrict__ Yext)
{
    extern __shared__ __align__(16) char smem[];
    __half2* s_scale2 = (__half2*)(smem + 4 * STG_B);
    __half2* s_shift2 = s_scale2 + 128;

    const int NCH = 4;                                   // K = 256, chunks of 64
    const int KW  = (MODE == 2) ? 256 : 512;             // w1 rows are 512 halves
    const __half* W = (MODE == 1) ? (const __half*)g_w1h
                    : (MODE == 2) ? (const __half*)g_w2h
                                  : (const __half*)g_w1h + 256;
    const __half* A = (MODE == 1) ? (const __half*)g_p1h
                    : (MODE == 3) ? (const __half*)g_p2h
                                  : (const __half*)g_yh;

    const int tid  = threadIdx.x;
    const int lane = tid & 31;
    const int wid  = tid >> 5;
    const int wm   = wid & 3;          // 4 warps along m (32 rows each)
    const int wn   = wid >> 2;         // 2 warps along n (64 cols each)
    const int m0   = blockIdx.y * 128;
    const int n0   = blockIdx.x * 128;

    if (MODE == 2 && tid < 128) {
        s_scale2[tid] = __floats2half2_rn(g_scale[2*tid], g_scale[2*tid+1]);
        s_shift2[tid] = __floats2half2_rn(g_shift[2*tid], g_shift[2*tid+1]);
    }

    const uint32_t smem_b = smem_u32(smem);
    const uint32_t sA[2] = { smem_b,             smem_b + STG_B };
    const uint32_t sB[2] = { smem_b + 2 * STG_B, smem_b + 3 * STG_B };
    const int lrow = tid >> 3;
    const int lc4  = tid & 7;

    auto cp_chunk = [&](int kt, int buf) {
        const int kcol = kt * 64;      // halves
        #pragma unroll
        for (int i = 0; i < 4; i++) {
            int row = lrow + i * 32;
            uint32_t soff = (uint32_t)(row * 144 + lc4 * 16);
            CP16(sA[buf] + soff, A + (size_t)(m0 + row) * C_ + kcol + lc4 * 8);
            CP16(sB[buf] + soff, W + (size_t)(n0 + row) * KW + kcol + lc4 * 8);
        }
        CP_COMMIT();
    };

    float c[2][8][4];
    #pragma unroll
    for (int mt = 0; mt < 2; mt++)
        #pragma unroll
        for (int nt = 0; nt < 8; nt++)
            #pragma unroll
            for (int j = 0; j < 4; j++) c[mt][nt][j] = 0.f;

    cp_chunk(0, 0);

    const int qk = lane & 3;
    const int qr = lane >> 2;
    const int lg  = lane >> 3;
    const int lr8 = lane & 7;
    // byte-identical tiling to the proven tf32 version (16B per k-group per row)
    const uint32_t aoff = (uint32_t)((wm * 32 + (lg & 1) * 8 + lr8) * 144 + (lg >> 1) * 16);
    const uint32_t boff = (uint32_t)((wn * 64 + (lg >> 1) * 8 + lr8) * 144 + (lg & 1) * 16);

    const __half2 zero2 = __float2half2_rn(0.f);

    for (int kt = 0; kt < NCH; kt++) {
        int buf = kt & 1;
        if (kt + 1 < NCH) { cp_chunk(kt + 1, buf ^ 1); CP_WAIT(1); }
        else              { CP_WAIT(0); }
        __syncthreads();

        const uint32_t aBase = sA[buf] + aoff;
        const uint32_t bBase = sB[buf] + boff;

        #pragma unroll
        for (int ks = 0; ks < 4; ks++) {      // k16 per step
            uint32_t a[2][4];
            #pragma unroll
            for (int mt = 0; mt < 2; mt++) {
                LDSM4(a[mt][0], a[mt][1], a[mt][2], a[mt][3],
                      aBase + mt * (16 * 144) + ks * 32);
                if (MODE == 2) {
                    int p0 = kt * 32 + ks * 8 + qk;   // half2 channel-pair index
                    int p1 = p0 + 4;
                    __half2 sc0 = s_scale2[p0], sh0 = s_shift2[p0];
                    __half2 sc1 = s_scale2[p1], sh1 = s_shift2[p1];
                    __half2* h = (__half2*)a[mt];
                    h[0] = __hmax2(__hfma2(h[0], sc0, sh0), zero2);
                    h[1] = __hmax2(__hfma2(h[1], sc0, sh0), zero2);
                    h[2] = __hmax2(__hfma2(h[2], sc1, sh1), zero2);
                    h[3] = __hmax2(__hfma2(h[3], sc1, sh1), zero2);
                }
            }
            uint32_t b[8][2];
            #pragma unroll
            for (int nt2 = 0; nt2 < 4; nt2++) {
                LDSM4(b[2*nt2][0], b[2*nt2][1], b[2*nt2+1][0], b[2*nt2+1][1],
                      bBase + nt2 * (16 * 144) + ks * 32);
            }
            #pragma unroll
            for (int mt = 0; mt < 2; mt++)
                #pragma unroll
                for (int nt = 0; nt < 8; nt++)
                    MMA_F16(c[mt][nt], a[mt], b[nt]);
        }
        __syncthreads();
    }

    // ---- MODE 1: add interpolated contribution  sum_j w_j * Z[idx_j]  (fp32) ----
    if (MODE == 1) {
        #pragma unroll
        for (int mt = 0; mt < 2; mt++) {
            #pragma unroll
            for (int h = 0; h < 2; h++) {
                int gr = m0 + wm * 32 + mt * 16 + qr + h * 8;
                const int*   id = g_idx + (size_t)gr * 3;
                const float* wt = g_w   + (size_t)gr * 3;
                int bb = (gr >> 12) << 10;
                const float* Z0 = g_z + (size_t)(bb + id[0]) * 256;
                const float* Z1 = g_z + (size_t)(bb + id[1]) * 256;
                const float* Z2 = g_z + (size_t)(bb + id[2]) * 256;
                float w0 = wt[0], w1 = wt[1], w2 = wt[2];
                #pragma unroll
                for (int nt = 0; nt < 8; nt++) {
                    int col = n0 + wn * 64 + nt * 8 + 2 * qk;
                    float2 z0 = *(const float2*)(Z0 + col);
                    float2 z1 = *(const float2*)(Z1 + col);
                    float2 z2 = *(const float2*)(Z2 + col);
                    c[mt][nt][2*h+0] += w0*z0.x + w1*z1.x + w2*z2.x;
                    c[mt][nt][2*h+1] += w0*z0.y + w1*z1.y + w2*z2.y;
                }
            }
        }
    }

    // ---- epilogue: write output ----
    #pragma unroll
    for (int mt = 0; mt < 2; mt++) {
        int row = m0 + wm * 32 + mt * 16 + qr;
        #pragma unroll
        for (int nt = 0; nt < 8; nt++) {
            int col = n0 + wn * 64 + nt * 8 + 2 * qk;
            if (MODE == 1) {
                *(__half2*)&g_yh[(size_t)row * 256 + col] =
                    __floats2half2_rn(c[mt][nt][0], c[mt][nt][1]);
                *(__half2*)&g_yh[(size_t)(row + 8) * 256 + col] =
                    __floats2half2_rn(c[mt][nt][2], c[mt][nt][3]);
            } else {
                float* Yo = (MODE == 3) ? (float*)g_z : Yext;
                *(float2*)&Yo[(size_t)row * 256 + col] =
                    make_float2(c[mt][nt][0], c[mt][nt][1]);
                *(float2*)&Yo[(size_t)(row + 8) * 256 + col] =
                    make_float2(c[mt][nt][2], c[mt][nt][3]);
            }
        }
    }

    // ---- fused BN stats (MODE 1 and 2 only) ----
    if (MODE != 3) {
        float* s_sum = (float*)smem;         // [4][128]
        float* s_sq  = (float*)smem + 512;   // [4][128]
        #pragma unroll
        for (int nt = 0; nt < 8; nt++) {
            #pragma unroll
            for (int p = 0; p < 2; p++) {
                float v0 = c[0][nt][p],     v1 = c[0][nt][p + 2];
                float v2 = c[1][nt][p],     v3 = c[1][nt][p + 2];
                float s  = (v0 + v1) + (v2 + v3);
                float s2 = fmaf(v0, v0, fmaf(v1, v1, fmaf(v2, v2, v3 * v3)));
                #pragma unroll
                for (int off = 4; off <= 16; off <<= 1) {
                    s  += __shfl_xor_sync(0xFFFFFFFFu, s,  off);
                    s2 += __shfl_xor_sync(0xFFFFFFFFu, s2, off);
                }
                if (qr == 0) {
                    int col = wn * 64 + nt * 8 + 2 * qk + p;
                    s_sum[wm * 128 + col] = s;
                    s_sq [wm * 128 + col] = s2;
                }
            }
        }
        __syncthreads();
        if (tid < 128) {
            int col = tid;
            float s  = (s_sum[col] + s_sum[128 + col]) + (s_sum[256 + col] + s_sum[384 + col]);
            float s2 = (s_sq [col] + s_sq [128 + col]) + (s_sq [256 + col] + s_sq [384 + col]);
            size_t slot = (size_t)blockIdx.y * 256 + blockIdx.x * 128 + col;
            g_psum[slot] = s;
            g_psq [slot] = s2;
        }
    }
}

// ---------------- BN finalize ----------------
__global__ void stats_finalize_kernel(const float* __restrict__ gamma,
                                      const float* __restrict__ beta)
{
    int c = threadIdx.x;
    float s = 0.f, s2 = 0.f;
    for (int i = 0; i < 512; i++) {
        s  += g_psum[i * 256 + c];
        s2 += g_psq [i * 256 + c];
    }
    const float invM = 1.0f / 65536.0f;
    float mu   = s * invM;
    float var  = fmaf(-mu, mu, s2 * invM);
    float rstd = rsqrtf(var + 1e-5f);
    float sc   = rstd * gamma[c];
    g_scale[c] = sc;
    g_shift[c] = fmaf(-mu, sc, beta[c]);
}

__global__ void norm_relu_kernel(float* Y)
{
    size_t i = (size_t)blockIdx.x * blockDim.x + threadIdx.x;  // float4 index
    int cg = (int)(i & 63) * 4;
    float4 v = *((float4*)Y + i);
    v.x = fmaxf(fmaf(v.x, __ldg(&g_scale[cg+0]), __ldg(&g_shift[cg+0])), 0.f);
    v.y = fmaxf(fmaf(v.y, __ldg(&g_scale[cg+1]), __ldg(&g_shift[cg+1])), 0.f);
    v.z = fmaxf(fmaf(v.z, __ldg(&g_scale[cg+2]), __ldg(&g_shift[cg+2])), 0.f);
    v.w = fmaxf(fmaf(v.w, __ldg(&g_scale[cg+3]), __ldg(&g_shift[cg+3])), 0.f);
    *((float4*)Y + i) = v;
}

// ---------------- launch ----------------
extern "C" void kernel_launch(void* const* d_in, const int* in_sizes, int n_in,
                              void* d_out, int out_size)
{
    const float* xyz1    = (const float*)d_in[0];
    const float* xyz2    = (const float*)d_in[1];
    const float* points1 = (const float*)d_in[2];
    const float* points2 = (const float*)d_in[3];
    const float* w1      = (const float*)d_in[4];
    const float* g1      = (const float*)d_in[5];
    const float* b1      = (const float*)d_in[6];
    const float* w2      = (const float*)d_in[7];
    const float* g2      = (const float*)d_in[8];
    const float* b2      = (const float*)d_in[9];
    float* out = (float*)d_out;

    cudaFuncSetAttribute(gemm_mma_kernel<1>, cudaFuncAttributeMaxDynamicSharedMemorySize, GSM_BYTES);
    cudaFuncSetAttribute(gemm_mma_kernel<2>, cudaFuncAttributeMaxDynamicSharedMemorySize, GSM_BYTES);
    cudaFuncSetAttribute(gemm_mma_kernel<3>, cudaFuncAttributeMaxDynamicSharedMemorySize, GSM_BYTES);

    const int CONV_TOTAL = S1_ + S2_ + S3_ + S4_;
    prep_convert_kernel<<<(CONV_TOTAL + 255) / 256, 256>>>(points1, points2, w1, w2);
    knn_kernel<<<dim3(N_ / 256, B_), 256>>>(xyz1, xyz2);

    // Z = p2 @ w1[:,256:]^T   (16384 x 256, fp32 out)
    gemm_mma_kernel<3><<<dim3(2, 128), 256, GSM_BYTES>>>(nullptr);

    // Y = p1 @ w1[:,:256]^T + gather(Z)  -> fp16 g_yh  (+ fused stats)
    gemm_mma_kernel<1><<<dim3(2, 512), 256, GSM_BYTES>>>(nullptr);
    stats_finalize_kernel<<<1, 256>>>(g1, b1);

    // out = relu(bn1(Y)) @ w2^T  (+ fused stats)
    gemm_mma_kernel<2><<<dim3(2, 512), 256, GSM_BYTES>>>(out);
    stats_finalize_kernel<<<1, 256>>>(g2, b2);
    norm_relu_kernel<<<16384, 256>>>(out);
}

// round 17
// speedup vs baseline: 1.3915x; 1.0264x over previous
#include <cuda_runtime.h>
#include <cuda_fp16.h>
#include <cstdint>

#define B_  16
#define N_  4096
#define S_  1024
#define C_  256
#define M_  (B_ * N_)   // 65536

// ---------------- scratch (no allocations allowed) ----------------
__device__ __half g_p1h[(size_t)M_ * C_];        // points1 fp16; REUSED after gemm1 as gemm2's fp16 output stage
__device__ __half g_p2h[(size_t)B_ * S_ * C_];   // points2 fp16
__device__ __half g_w1h[256 * 512];              // w1 fp16
__device__ __half g_w2h[256 * 256];              // w2 fp16
__device__ __half g_yh[(size_t)M_ * C_];         // hidden y fp16 (pre-BN)
__device__ __half g_zh[(size_t)B_ * S_ * C_];    // Z = points2 @ w1[:,256:]^T (fp16)
__device__ int    g_idx[M_ * 3];
__device__ float  g_w[M_ * 3];
__device__ float  g_psum[512 * 256];
__device__ float  g_psq [512 * 256];
__device__ float  g_scale[256];
__device__ float  g_shift[256];

// ---------------- PTX helpers (family-portable, sm_80+) ----------------
__device__ __forceinline__ uint32_t smem_u32(const void* p) {
    uint32_t a;
    asm("{ .reg .u64 t; cvta.to.shared.u64 t, %1; cvt.u32.u64 %0, t; }" : "=r"(a) : "l"(p));
    return a;
}
#define CP16(dst, src) \
    asm volatile("cp.async.cg.shared.global [%0], [%1], 16;" :: "r"(dst), "l"(src) : "memory")
#define CP_COMMIT() asm volatile("cp.async.commit_group;" ::: "memory")
#define CP_WAIT(N)  asm volatile("cp.async.wait_group %0;" :: "n"(N) : "memory")

#define MMA_F16(c, a, b) \
    asm volatile("mma.sync.aligned.m16n8k16.row.col.f32.f16.f16.f32 " \
        "{%0,%1,%2,%3}, {%4,%5,%6,%7}, {%8,%9}, {%0,%1,%2,%3};" \
        : "+f"((c)[0]), "+f"((c)[1]), "+f"((c)[2]), "+f"((c)[3]) \
        : "r"((a)[0]), "r"((a)[1]), "r"((a)[2]), "r"((a)[3]), \
          "r"((b)[0]), "r"((b)[1]))

#define LDSM4(r0, r1, r2, r3, addr) \
    asm volatile("ldmatrix.sync.aligned.m8n8.x4.shared.b16 {%0,%1,%2,%3}, [%4];" \
        : "=r"(r0), "=r"(r1), "=r"(r2), "=r"(r3) : "r"(addr))

// ---------------- prep: convert inputs to fp16 once ----------------
#define S1_ (M_ * C_ / 4)                 // points1 float4 count
#define S2_ (B_ * S_ * C_ / 4)
#define S3_ (256 * 512 / 4)
#define S4_ (256 * 256 / 4)
__global__ void prep_convert_kernel(const float* __restrict__ p1,
                                    const float* __restrict__ p2,
                                    const float* __restrict__ w1,
                                    const float* __restrict__ w2)
{
    size_t i = (size_t)blockIdx.x * blockDim.x + threadIdx.x;
    const float4* src; __half2* dst; size_t off;
    if      (i < S1_)                 { src = (const float4*)p1; dst = (__half2*)g_p1h; off = i; }
    else if (i < S1_ + S2_)           { src = (const float4*)p2; dst = (__half2*)g_p2h; off = i - S1_; }
    else if (i < S1_ + S2_ + S3_)     { src = (const float4*)w1; dst = (__half2*)g_w1h; off = i - S1_ - S2_; }
    else if (i < S1_ + S2_ + S3_ + S4_){ src = (const float4*)w2; dst = (__half2*)g_w2h; off = i - S1_ - S2_ - S3_; }
    else return;
    float4 v = src[off];
    dst[off * 2 + 0] = __floats2half2_rn(v.x, v.y);
    dst[off * 2 + 1] = __floats2half2_rn(v.z, v.w);
}

// ---------------- 3-NN (idx + weights) ----------------
__global__ void knn_kernel(const float* __restrict__ xyz1,
                           const float* __restrict__ xyz2)
{
    __shared__ __align__(16) float4 sp[S_];
    int b = blockIdx.y;
    const float* X2 = xyz2 + (size_t)b * S_ * 3;
    for (int i = threadIdx.x; i < S_; i += blockDim.x) {
        float x = X2[i*3+0], y = X2[i*3+1], z = X2[i*3+2];
        sp[i] = make_float4(x, y, z, x*x + y*y + z*z);
    }
    __syncthreads();

    int n = blockIdx.x * blockDim.x + threadIdx.x;
    const float* p = xyz1 + ((size_t)b * N_ + n) * 3;
    float x1 = p[0], y1 = p[1], z1 = p[2];
    float s1 = x1*x1 + y1*y1 + z1*z1;

    float d0 = 3.4e38f, d1 = 3.4e38f, d2 = 3.4e38f;
    int   i0 = 0, i1 = 0, i2 = 0;
    #pragma unroll 4
    for (int s = 0; s < S_; s++) {
        float4 q = sp[s];
        float dot = fmaf(x1, q.x, fmaf(y1, q.y, z1 * q.z));
        float d   = fmaf(-2.0f, dot, s1 + q.w);
        if (d < d2) {
            if (d < d1) {
                d2 = d1; i2 = i1;
                if (d < d0) { d1 = d0; i1 = i0; d0 = d; i0 = s; }
                else        { d1 = d;  i1 = s; }
            } else { d2 = d; i2 = s; }
        }
    }
    float r0 = 1.0f / (d0 + 1e-8f);
    float r1 = 1.0f / (d1 + 1e-8f);
    float r2 = 1.0f / (d2 + 1e-8f);
    float inv = 1.0f / (r0 + r1 + r2);
    size_t o = ((size_t)b * N_ + n) * 3;
    g_idx[o+0] = i0; g_idx[o+1] = i1; g_idx[o+2] = i2;
    g_w[o+0] = r0 * inv; g_w[o+1] = r1 * inv; g_w[o+2] = r2 * inv;
}

// ---------------- fp16 mma.sync GEMM (2-stage cp.async, ldmatrix) ----------------
// All modes: K = 256 (4 chunks of 64), CTA tile 128x128, all outputs fp16.
// A/W/out resolved INSIDE device code (device symbols; R15 lesson).
// MODE 3: A = g_p2h, W = w1[:,256:] -> g_zh               (grid 2 x 128)
// MODE 1: A = g_p1h, W = w1[:,:256], + gather(Z) -> g_yh, fused BN stats (grid 2 x 512)
// MODE 2: A = relu(bn1(g_yh)) half2-fused, W = w2 -> g_p1h (staging), fused BN stats
#define STG_B  18432                     // 128 rows * 144 bytes
#define GSM_BYTES (4 * STG_B + 1024)     // 74752 B

template<int MODE>
__global__ __launch_bounds__(256, 2)
void gemm_mma_kernel()
{
    extern __shared__ __align__(16) char smem[];
    __half2* s_scale2 = (__half2*)(smem + 4 * STG_B);
    __half2* s_shift2 = s_scale2 + 128;

    const int NCH = 4;                                   // K = 256, chunks of 64
    const int KW  = (MODE == 2) ? 256 : 512;             // w1 rows are 512 halves
    const __half* W = (MODE == 1) ? (const __half*)g_w1h
                    : (MODE == 2) ? (const __half*)g_w2h
                                  : (const __half*)g_w1h + 256;
    const __half* A = (MODE == 1) ? (const __half*)g_p1h
                    : (MODE == 3) ? (const __half*)g_p2h
                                  : (const __half*)g_yh;
    __half* Yo = (MODE == 1) ? (__half*)g_yh
               : (MODE == 3) ? (__half*)g_zh
                             : (__half*)g_p1h;           // MODE 2: reuse dead p1h as staging

    const int tid  = threadIdx.x;
    const int lane = tid & 31;
    const int wid  = tid >> 5;
    const int wm   = wid & 3;          // 4 warps along m (32 rows each)
    const int wn   = wid >> 2;         // 2 warps along n (64 cols each)
    const int m0   = blockIdx.y * 128;
    const int n0   = blockIdx.x * 128;

    if (MODE == 2 && tid < 128) {
        s_scale2[tid] = __floats2half2_rn(g_scale[2*tid], g_scale[2*tid+1]);
        s_shift2[tid] = __floats2half2_rn(g_shift[2*tid], g_shift[2*tid+1]);
    }

    const uint32_t smem_b = smem_u32(smem);
    const uint32_t sA[2] = { smem_b,             smem_b + STG_B };
    const uint32_t sB[2] = { smem_b + 2 * STG_B, smem_b + 3 * STG_B };
    const int lrow = tid >> 3;
    const int lc4  = tid & 7;

    auto cp_chunk = [&](int kt, int buf) {
        const int kcol = kt * 64;      // halves
        #pragma unroll
        for (int i = 0; i < 4; i++) {
            int row = lrow + i * 32;
            uint32_t soff = (uint32_t)(row * 144 + lc4 * 16);
            CP16(sA[buf] + soff, A + (size_t)(m0 + row) * C_ + kcol + lc4 * 8);
            CP16(sB[buf] + soff, W + (size_t)(n0 + row) * KW + kcol + lc4 * 8);
        }
        CP_COMMIT();
    };

    float c[2][8][4];
    #pragma unroll
    for (int mt = 0; mt < 2; mt++)
        #pragma unroll
        for (int nt = 0; nt < 8; nt++)
            #pragma unroll
            for (int j = 0; j < 4; j++) c[mt][nt][j] = 0.f;

    cp_chunk(0, 0);

    const int qk = lane & 3;
    const int qr = lane >> 2;
    const int lg  = lane >> 3;
    const int lr8 = lane & 7;
    const uint32_t aoff = (uint32_t)((wm * 32 + (lg & 1) * 8 + lr8) * 144 + (lg >> 1) * 16);
    const uint32_t boff = (uint32_t)((wn * 64 + (lg >> 1) * 8 + lr8) * 144 + (lg & 1) * 16);

    const __half2 zero2 = __float2half2_rn(0.f);

    for (int kt = 0; kt < NCH; kt++) {
        int buf = kt & 1;
        if (kt + 1 < NCH) { cp_chunk(kt + 1, buf ^ 1); CP_WAIT(1); }
        else              { CP_WAIT(0); }
        __syncthreads();

        const uint32_t aBase = sA[buf] + aoff;
        const uint32_t bBase = sB[buf] + boff;

        #pragma unroll
        for (int ks = 0; ks < 4; ks++) {      // k16 per step
            uint32_t a[2][4];
            #pragma unroll
            for (int mt = 0; mt < 2; mt++) {
                LDSM4(a[mt][0], a[mt][1], a[mt][2], a[mt][3],
                      aBase + mt * (16 * 144) + ks * 32);
                if (MODE == 2) {
                    int p0 = kt * 32 + ks * 8 + qk;   // half2 channel-pair index
                    int p1 = p0 + 4;
                    __half2 sc0 = s_scale2[p0], sh0 = s_shift2[p0];
                    __half2 sc1 = s_scale2[p1], sh1 = s_shift2[p1];
                    __half2* h = (__half2*)a[mt];
                    h[0] = __hmax2(__hfma2(h[0], sc0, sh0), zero2);
                    h[1] = __hmax2(__hfma2(h[1], sc0, sh0), zero2);
                    h[2] = __hmax2(__hfma2(h[2], sc1, sh1), zero2);
                    h[3] = __hmax2(__hfma2(h[3], sc1, sh1), zero2);
                }
            }
            uint32_t b[8][2];
            #pragma unroll
            for (int nt2 = 0; nt2 < 4; nt2++) {
                LDSM4(b[2*nt2][0], b[2*nt2][1], b[2*nt2+1][0], b[2*nt2+1][1],
                      bBase + nt2 * (16 * 144) + ks * 32);
            }
            #pragma unroll
            for (int mt = 0; mt < 2; mt++)
                #pragma unroll
                for (int nt = 0; nt < 8; nt++)
                    MMA_F16(c[mt][nt], a[mt], b[nt]);
        }
        __syncthreads();
    }

    // ---- MODE 1: add interpolated contribution  sum_j w_j * Z[idx_j]  (Z fp16, accum fp32) ----
    if (MODE == 1) {
        #pragma unroll
        for (int mt = 0; mt < 2; mt++) {
            #pragma unroll
            for (int h = 0; h < 2; h++) {
                int gr = m0 + wm * 32 + mt * 16 + qr + h * 8;
                const int*   id = g_idx + (size_t)gr * 3;
                const float* wt = g_w   + (size_t)gr * 3;
                int bb = (gr >> 12) << 10;
                const __half* Z0 = g_zh + (size_t)(bb + id[0]) * 256;
                const __half* Z1 = g_zh + (size_t)(bb + id[1]) * 256;
                const __half* Z2 = g_zh + (size_t)(bb + id[2]) * 256;
                float w0 = wt[0], w1 = wt[1], w2 = wt[2];
                #pragma unroll
                for (int nt = 0; nt < 8; nt++) {
                    int col = n0 + wn * 64 + nt * 8 + 2 * qk;
                    float2 z0 = __half22float2(*(const __half2*)(Z0 + col));
                    float2 z1 = __half22float2(*(const __half2*)(Z1 + col));
                    float2 z2 = __half22float2(*(const __half2*)(Z2 + col));
                    c[mt][nt][2*h+0] += w0*z0.x + w1*z1.x + w2*z2.x;
                    c[mt][nt][2*h+1] += w0*z0.y + w1*z1.y + w2*z2.y;
                }
            }
        }
    }

    // ---- epilogue: write fp16 output ----
    #pragma unroll
    for (int mt = 0; mt < 2; mt++) {
        int row = m0 + wm * 32 + mt * 16 + qr;
        #pragma unroll
        for (int nt = 0; nt < 8; nt++) {
            int col = n0 + wn * 64 + nt * 8 + 2 * qk;
            *(__half2*)&Yo[(size_t)row * 256 + col] =
                __floats2half2_rn(c[mt][nt][0], c[mt][nt][1]);
            *(__half2*)&Yo[(size_t)(row + 8) * 256 + col] =
                __floats2half2_rn(c[mt][nt][2], c[mt][nt][3]);
        }
    }

    // ---- fused BN stats (MODE 1 and 2 only; from fp32 accumulators) ----
    if (MODE != 3) {
        float* s_sum = (float*)smem;         // [4][128]
        float* s_sq  = (float*)smem + 512;   // [4][128]
        #pragma unroll
        for (int nt = 0; nt < 8; nt++) {
            #pragma unroll
            for (int p = 0; p < 2; p++) {
                float v0 = c[0][nt][p],     v1 = c[0][nt][p + 2];
                float v2 = c[1][nt][p],     v3 = c[1][nt][p + 2];
                float s  = (v0 + v1) + (v2 + v3);
                float s2 = fmaf(v0, v0, fmaf(v1, v1, fmaf(v2, v2, v3 * v3)));
                #pragma unroll
                for (int off = 4; off <= 16; off <<= 1) {
                    s  += __shfl_xor_sync(0xFFFFFFFFu, s,  off);
                    s2 += __shfl_xor_sync(0xFFFFFFFFu, s2, off);
                }
                if (qr == 0) {
                    int col = wn * 64 + nt * 8 + 2 * qk + p;
                    s_sum[wm * 128 + col] = s;
                    s_sq [wm * 128 + col] = s2;
                }
            }
        }
        __syncthreads();
        if (tid < 128) {
            int col = tid;
            float s  = (s_sum[col] + s_sum[128 + col]) + (s_sum[256 + col] + s_sum[384 + col]);
            float s2 = (s_sq [col] + s_sq [128 + col]) + (s_sq [256 + col] + s_sq [384 + col]);
            size_t slot = (size_t)blockIdx.y * 256 + blockIdx.x * 128 + col;
            g_psum[slot] = s;
            g_psq [slot] = s2;
        }
    }
}

// ---------------- BN finalize ----------------
__global__ void stats_finalize_kernel(const float* __restrict__ gamma,
                                      const float* __restrict__ beta)
{
    int c = threadIdx.x;
    float s = 0.f, s2 = 0.f;
    for (int i = 0; i < 512; i++) {
        s  += g_psum[i * 256 + c];
        s2 += g_psq [i * 256 + c];
    }
    const float invM = 1.0f / 65536.0f;
    float mu   = s * invM;
    float var  = fmaf(-mu, mu, s2 * invM);
    float rstd = rsqrtf(var + 1e-5f);
    float sc   = rstd * gamma[c];
    g_scale[c] = sc;
    g_shift[c] = fmaf(-mu, sc, beta[c]);
}

// BN2 + ReLU: read staged fp16 (g_p1h), write fp32 d_out
__global__ void norm_relu_kernel(float* __restrict__ Y)
{
    size_t i = (size_t)blockIdx.x * blockDim.x + threadIdx.x;  // float4 index
    int cg = (int)(i & 63) * 4;
    const __half2* src = (const __half2*)g_p1h;
    float2 f0 = __half22float2(src[2 * i]);
    float2 f1 = __half22float2(src[2 * i + 1]);
    float4 v;
    v.x = fmaxf(fmaf(f0.x, __ldg(&g_scale[cg+0]), __ldg(&g_shift[cg+0])), 0.f);
    v.y = fmaxf(fmaf(f0.y, __ldg(&g_scale[cg+1]), __ldg(&g_shift[cg+1])), 0.f);
    v.z = fmaxf(fmaf(f1.x, __ldg(&g_scale[cg+2]), __ldg(&g_shift[cg+2])), 0.f);
    v.w = fmaxf(fmaf(f1.y, __ldg(&g_scale[cg+3]), __ldg(&g_shift[cg+3])), 0.f);
    *((float4*)Y + i) = v;
}

// ---------------- launch ----------------
extern "C" void kernel_launch(void* const* d_in, const int* in_sizes, int n_in,
                              void* d_out, int out_size)
{
    const float* xyz1    = (const float*)d_in[0];
    const float* xyz2    = (const float*)d_in[1];
    const float* points1 = (const float*)d_in[2];
    const float* points2 = (const float*)d_in[3];
    const float* w1      = (const float*)d_in[4];
    const float* g1      = (const float*)d_in[5];
    const float* b1      = (const float*)d_in[6];
    const float* w2      = (const float*)d_in[7];
    const float* g2      = (const float*)d_in[8];
    const float* b2      = (const float*)d_in[9];
    float* out = (float*)d_out;

    cudaFuncSetAttribute(gemm_mma_kernel<1>, cudaFuncAttributeMaxDynamicSharedMemorySize, GSM_BYTES);
    cudaFuncSetAttribute(gemm_mma_kernel<2>, cudaFuncAttributeMaxDynamicSharedMemorySize, GSM_BYTES);
    cudaFuncSetAttribute(gemm_mma_kernel<3>, cudaFuncAttributeMaxDynamicSharedMemorySize, GSM_BYTES);

    const int CONV_TOTAL = S1_ + S2_ + S3_ + S4_;
    prep_convert_kernel<<<(CONV_TOTAL + 255) / 256, 256>>>(points1, points2, w1, w2);
    knn_kernel<<<dim3(N_ / 256, B_), 256>>>(xyz1, xyz2);

    // Z = p2 @ w1[:,256:]^T   (16384 x 256, fp16 out)
    gemm_mma_kernel<3><<<dim3(2, 128), 256, GSM_BYTES>>>();

    // Y = p1 @ w1[:,:256]^T + gather(Z)  -> fp16 g_yh  (+ fused stats)
    gemm_mma_kernel<1><<<dim3(2, 512), 256, GSM_BYTES>>>();
    stats_finalize_kernel<<<1, 256>>>(g1, b1);

    // tmp = relu(bn1(Y)) @ w2^T -> fp16 staging in g_p1h  (+ fused stats)
    gemm_mma_kernel<2><<<dim3(2, 512), 256, GSM_BYTES>>>();
    stats_finalize_kernel<<<1, 256>>>(g2, b2);

    // out = relu(bn2(tmp))  (fp16 read, fp32 write)
    norm_relu_kernel<<<16384, 256>>>(out);
}